// round 11
// baseline (speedup 1.0000x reference)
#include <cuda_runtime.h>

#define POOL 7
#define NUM_ROIS 300
#define IMG_H 200
#define IMG_W 200
#define IMG_C 512

#define CP16(dst_u32, src) \
    asm volatile("cp.async.cg.shared.global [%0], [%1], 16;" :: "r"(dst_u32), "l"(src))
#define CP_COMMIT() asm volatile("cp.async.commit_group;")
#define CP_WAIT(N)  asm volatile("cp.async.wait_group %0;" :: "n"(N))

__device__ __forceinline__ unsigned su32(const void* p) {
    return (unsigned)__cvta_generic_to_shared(p);
}

__device__ __forceinline__ float4 lerp4(float4 a, float4 b, float ga, float fb)
{
    float4 r;
    r.x = a.x * ga + b.x * fb;
    r.y = a.y * ga + b.y * fb;
    r.z = a.z * ga + b.z * fb;
    r.w = a.w * ga + b.w * fb;
    return r;
}

struct HCoord { int e0, e1; float fx; bool needX; };

__device__ __forceinline__ HCoord hcoord(int px, float sx, int w, int x0)
{
    HCoord hc;
    const float xs = (float)px * sx;
    int ix0 = (int)floorf(xs);
    hc.fx = xs - (float)ix0;            // frac BEFORE clamp (matches ref)
    ix0 = min(ix0, w - 1);
    const int ix1 = min(ix0 + 1, w - 1);
    hc.needX = (hc.fx != 0.0f) && (ix1 != ix0);
    hc.e0 = (x0 + ix0) * IMG_C;
    hc.e1 = (x0 + ix1) * IMG_C;
    return hc;
}

// Issue cp.asyncs for one px into its [4][128] corner buffer (skip dead loads).
__device__ __forceinline__ void prefetch_px(
    float4 (&pb)[4][128], const float* __restrict__ row0,
    const float* __restrict__ row1, bool needY, const HCoord& hc, int t)
{
    CP16(su32(&pb[0][t]), row0 + hc.e0);
    if (hc.needX) CP16(su32(&pb[1][t]), row0 + hc.e1);
    if (needY) {
        CP16(su32(&pb[2][t]), row1 + hc.e0);
        if (hc.needX) CP16(su32(&pb[3][t]), row1 + hc.e1);
    }
}

// Consume one px's buffered corners, interpolate, store.
__device__ __forceinline__ void compute_px(
    const float4 (&pb)[4][128], float* __restrict__ obase, int px,
    bool needY, float fy, const HCoord& hc, int t)
{
    const float gx = 1.0f - hc.fx;
    const float gy = 1.0f - fy;

    const float4 v00 = pb[0][t];
    float4 top = hc.needX ? lerp4(v00, pb[1][t], gx, hc.fx) : v00;
    float4 r;
    if (needY) {
        const float4 v10 = pb[2][t];
        const float4 bot = hc.needX ? lerp4(v10, pb[3][t], gx, hc.fx) : v10;
        r = lerp4(top, bot, gy, fy);
    } else {
        r = top;
    }
    __stcs((float4*)(obase + px * IMG_C), r);
}

// One block per (roi, py, px-quarter): quarters {0,1},{2,3},{4,5},{6}.
// 128 threads, 4 channels each. All GMEM reads go through cp.async into a
// 16 KB SMEM buffer (register-free MLP up to 8 copies/thread) at 14 CTAs/SM.
// Thread-private buffer slots -> no __syncthreads needed.
__global__ __launch_bounds__(128) void roi_pool_kernel(
    const float* __restrict__ img,   // [H, W, C]
    const float* __restrict__ rois,  // [NUM_ROIS, 4] (x, y, w, h) as float
    float* __restrict__ out)         // [NUM_ROIS, POOL, POOL, C]
{
    __shared__ float4 buf[2][4][128];      // [pxInPair][corner][tid] = 16 KB

    const int b    = blockIdx.x;           // 0..8399
    const int q    = b & 3;                // px-quarter
    const int rp   = b >> 2;               // roi*7 + py
    const int roi  = rp / POOL;
    const int py   = rp - roi * POOL;
    const int t    = threadIdx.x;
    const int c    = t * 4;

    // ---- ROI geometry (uniform across block) ----
    const int rx = (int)__ldg(&rois[roi * 4 + 0]);
    const int ry = (int)__ldg(&rois[roi * 4 + 1]);
    const int rw = (int)__ldg(&rois[roi * 4 + 2]);
    const int rh = (int)__ldg(&rois[roi * 4 + 3]);

    const int x0 = min(max(rx, 0), IMG_W - 1);
    const int y0 = min(max(ry, 0), IMG_H - 1);
    const int w  = min(max(rw, 1), IMG_W - x0);
    const int h  = min(max(rh, 1), IMG_H - y0);

    // TF1 resize (align_corners=False): src = dst * (in/out); exact fp32 div
    const float sx = (float)w / (float)POOL;
    const float sy = (float)h / (float)POOL;

    // ---- vertical coords (fixed for this block) ----
    const float ys = (float)py * sy;
    int iy0 = (int)floorf(ys);
    const float fy = ys - (float)iy0;      // frac BEFORE clamp
    iy0 = min(iy0, h - 1);
    const int iy1 = min(iy0 + 1, h - 1);
    const bool needY = (fy != 0.0f) && (iy1 != iy0);

    const float* __restrict__ row0 = img + (long)((y0 + iy0) * IMG_W) * IMG_C + c;
    const float* __restrict__ row1 = img + (long)((y0 + iy1) * IMG_W) * IMG_C + c;
    float* __restrict__ obase = out + (long)rp * (POOL * IMG_C) + c;

    const int px0 = q * 2;                 // 0,2,4,6
    const bool has2nd = (q != 3);          // quarter 3 covers only px=6

    const HCoord h0 = hcoord(px0, sx, w, x0);
    HCoord h1;
    if (has2nd) h1 = hcoord(px0 + 1, sx, w, x0);

    // ---- issue ALL loads up front, register-free ----
    prefetch_px(buf[0], row0, row1, needY, h0, t);
    if (has2nd) prefetch_px(buf[1], row0, row1, needY, h1, t);
    CP_COMMIT();

    // ---- drain + compute ----
    CP_WAIT(0);
    compute_px(buf[0], obase, px0, needY, fy, h0, t);
    if (has2nd) compute_px(buf[1], obase, px0 + 1, needY, fy, h1, t);
}

extern "C" void kernel_launch(void* const* d_in, const int* in_sizes, int n_in,
                              void* d_out, int out_size)
{
    const float* img  = (const float*)d_in[0];
    const float* rois = (const float*)d_in[1];
    float* out = (float*)d_out;

    const int nblocks = NUM_ROIS * POOL * 4;  // 8400
    roi_pool_kernel<<<nblocks, 128>>>(img, rois, out);
}

// round 14
// speedup vs baseline: 1.0373x; 1.0373x over previous
#include <cuda_runtime.h>

#define POOL 7
#define NUM_ROIS 300
#define IMG_H 200
#define IMG_W 200
#define IMG_C 512

#define CP16(dst_u32, src) \
    asm volatile("cp.async.cg.shared.global [%0], [%1], 16;" :: "r"(dst_u32), "l"(src))
#define CP_COMMIT() asm volatile("cp.async.commit_group;")
#define CP_WAIT(N)  asm volatile("cp.async.wait_group %0;" :: "n"(N))

__device__ __forceinline__ unsigned su32(const void* p) {
    return (unsigned)__cvta_generic_to_shared(p);
}

__device__ __forceinline__ float4 lerp4(float4 a, float4 b, float ga, float fb)
{
    float4 r;
    r.x = a.x * ga + b.x * fb;
    r.y = a.y * ga + b.y * fb;
    r.z = a.z * ga + b.z * fb;
    r.w = a.w * ga + b.w * fb;
    return r;
}

struct HCoord { int e0, e1; float fx; bool needX; };

__device__ __forceinline__ HCoord hcoord(int px, float sx, int w, int x0)
{
    HCoord hc;
    const float xs = (float)px * sx;
    int ix0 = (int)floorf(xs);
    hc.fx = xs - (float)ix0;            // frac BEFORE clamp (matches ref)
    ix0 = min(ix0, w - 1);
    const int ix1 = min(ix0 + 1, w - 1);
    hc.needX = (hc.fx != 0.0f) && (ix1 != ix0);
    hc.e0 = (x0 + ix0) * IMG_C;
    hc.e1 = (x0 + ix1) * IMG_C;
    return hc;
}

// Issue cp.asyncs for one px into its [4][128] corner buffer (skip dead loads).
__device__ __forceinline__ void prefetch_px(
    float4 (&pb)[4][128], const float* __restrict__ row0,
    const float* __restrict__ row1, bool needY, const HCoord& hc, int t)
{
    CP16(su32(&pb[0][t]), row0 + hc.e0);
    if (hc.needX) CP16(su32(&pb[1][t]), row0 + hc.e1);
    if (needY) {
        CP16(su32(&pb[2][t]), row1 + hc.e0);
        if (hc.needX) CP16(su32(&pb[3][t]), row1 + hc.e1);
    }
}

// Consume one px's buffered corners, interpolate, store.
__device__ __forceinline__ void compute_px(
    const float4 (&pb)[4][128], float* __restrict__ obase, int px,
    bool needY, float fy, const HCoord& hc, int t)
{
    const float gx = 1.0f - hc.fx;
    const float gy = 1.0f - fy;

    const float4 v00 = pb[0][t];
    float4 top = hc.needX ? lerp4(v00, pb[1][t], gx, hc.fx) : v00;
    float4 r;
    if (needY) {
        const float4 v10 = pb[2][t];
        const float4 bot = hc.needX ? lerp4(v10, pb[3][t], gx, hc.fx) : v10;
        r = lerp4(top, bot, gy, fy);
    } else {
        r = top;
    }
    __stcs((float4*)(obase + px * IMG_C), r);
}

// One block per (roi, py, px-half): half 0 -> px {0..3}, half 1 -> px {4..6}.
// 128 threads, 4 channels each. All GMEM reads go through cp.async into SMEM
// (register-free MLP). Four commit groups with progressive wait_group drains:
// compute/store of early px overlaps the in-flight loads of later px.
// Thread-private buffer slots -> no __syncthreads needed.
__global__ __launch_bounds__(128) void roi_pool_kernel(
    const float* __restrict__ img,   // [H, W, C]
    const float* __restrict__ rois,  // [NUM_ROIS, 4] (x, y, w, h) as float
    float* __restrict__ out)         // [NUM_ROIS, POOL, POOL, C]
{
    __shared__ float4 buf[4][4][128];      // [pxSlot][corner][tid] = 32 KB

    const int b    = blockIdx.x;           // 0..4199
    const int half = b & 1;
    const int rp   = b >> 1;               // roi*7 + py
    const int roi  = rp / POOL;
    const int py   = rp - roi * POOL;
    const int t    = threadIdx.x;
    const int c    = t * 4;

    // ---- ROI geometry (uniform across block) ----
    const int rx = (int)__ldg(&rois[roi * 4 + 0]);
    const int ry = (int)__ldg(&rois[roi * 4 + 1]);
    const int rw = (int)__ldg(&rois[roi * 4 + 2]);
    const int rh = (int)__ldg(&rois[roi * 4 + 3]);

    const int x0 = min(max(rx, 0), IMG_W - 1);
    const int y0 = min(max(ry, 0), IMG_H - 1);
    const int w  = min(max(rw, 1), IMG_W - x0);
    const int h  = min(max(rh, 1), IMG_H - y0);

    // TF1 resize (align_corners=False): src = dst * (in/out); exact fp32 div
    const float sx = (float)w / (float)POOL;
    const float sy = (float)h / (float)POOL;

    // ---- vertical coords (fixed for this block) ----
    const float ys = (float)py * sy;
    int iy0 = (int)floorf(ys);
    const float fy = ys - (float)iy0;      // frac BEFORE clamp
    iy0 = min(iy0, h - 1);
    const int iy1 = min(iy0 + 1, h - 1);
    const bool needY = (fy != 0.0f) && (iy1 != iy0);

    const float* __restrict__ row0 = img + (long)((y0 + iy0) * IMG_W) * IMG_C + c;
    const float* __restrict__ row1 = img + (long)((y0 + iy1) * IMG_W) * IMG_C + c;
    float* __restrict__ obase = out + (long)rp * (POOL * IMG_C) + c;

    const int px0 = half ? 4 : 0;
    const bool has4th = (half == 0);       // half 1 covers only 3 px

    const HCoord h0 = hcoord(px0,     sx, w, x0);
    const HCoord h1 = hcoord(px0 + 1, sx, w, x0);
    const HCoord h2 = hcoord(px0 + 2, sx, w, x0);
    HCoord h3;
    if (has4th) h3 = hcoord(px0 + 3, sx, w, x0);

    // ---- issue ALL loads up front, one commit group per px ----
    prefetch_px(buf[0], row0, row1, needY, h0, t);
    CP_COMMIT();
    prefetch_px(buf[1], row0, row1, needY, h1, t);
    CP_COMMIT();
    prefetch_px(buf[2], row0, row1, needY, h2, t);
    CP_COMMIT();
    if (has4th) prefetch_px(buf[3], row0, row1, needY, h3, t);
    CP_COMMIT();

    // ---- progressive drain + compute (overlap compute with later loads) ----
    CP_WAIT(3);
    compute_px(buf[0], obase, px0, needY, fy, h0, t);
    CP_WAIT(2);
    compute_px(buf[1], obase, px0 + 1, needY, fy, h1, t);
    CP_WAIT(1);
    compute_px(buf[2], obase, px0 + 2, needY, fy, h2, t);
    if (has4th) {
        CP_WAIT(0);
        compute_px(buf[3], obase, px0 + 3, needY, fy, h3, t);
    }
}

extern "C" void kernel_launch(void* const* d_in, const int* in_sizes, int n_in,
                              void* d_out, int out_size)
{
    const float* img  = (const float*)d_in[0];
    const float* rois = (const float*)d_in[1];
    float* out = (float*)d_out;

    const int nblocks = NUM_ROIS * POOL * 2;  // 4200
    roi_pool_kernel<<<nblocks, 128>>>(img, rois, out);
}